// round 16
// baseline (speedup 1.0000x reference)
#include <cuda_runtime.h>
#include <cuda_fp16.h>
#include <cstdint>

// Problem dims (fixed by the dataset)
#define B_ 64
#define T_ 2048
#define I_ 256
#define H_ 256
#define G4_ 1024  // 4*H

// Scratch for the input projection xz = x@Wx + b : [B,T,4H] fp32 (537 MB).
__device__ float g_xz[(size_t)B_ * T_ * G4_];

// Pack two floats into fp16x2 bits (full 32-bit, both halves)
__device__ __forceinline__ unsigned pack_h2(float a, float b) {
    __half2 h = __floats2half2_rn(a, b);
    return *reinterpret_cast<unsigned*>(&h);
}

// ---------------------------------------------------------------------------
// Kernel 1: xz = x@Wx + b via fp16 tensor cores (mma.sync.m16n8k16, f32 acc).
// (unchanged — known good, ~0.5 ms)
// ---------------------------------------------------------------------------
__global__ __launch_bounds__(256) void gemm_xz_mma(
    const float* __restrict__ x, const float* __restrict__ Wx,
    const float* __restrict__ bias)
{
    __shared__ __half As[128][72];
    __shared__ __half Bs[128][72];

    const int tid  = threadIdx.x;
    const int warp = tid >> 5;
    const int lane = tid & 31;
    const int g    = lane >> 2;
    const int tg   = lane & 3;

    const int m0 = blockIdx.y * 128;
    const int n0 = blockIdx.x * 128;
    const int wm = (warp & 3) * 32;
    const int wn = (warp >> 2) * 64;

    float d[2][8][4];
#pragma unroll
    for (int mt = 0; mt < 2; mt++)
#pragma unroll
        for (int nt = 0; nt < 8; nt++)
#pragma unroll
            for (int q = 0; q < 4; q++) d[mt][nt][q] = 0.f;

    const int sr = tid >> 1;
    const int sk = (tid & 1) * 32;

    for (int k0 = 0; k0 < 256; k0 += 64) {
        {
            const float4* xp = reinterpret_cast<const float4*>(
                &x[(size_t)(m0 + sr) * 256 + k0 + sk]);
#pragma unroll
            for (int i = 0; i < 8; i++) {
                float4 v = xp[i];
                *reinterpret_cast<__half2*>(&As[sr][sk + 4 * i])     = __floats2half2_rn(v.x, v.y);
                *reinterpret_cast<__half2*>(&As[sr][sk + 4 * i + 2]) = __floats2half2_rn(v.z, v.w);
            }
        }
        {
#pragma unroll
            for (int i = 0; i < 16; i++) {
                float w0 = __ldg(&Wx[(size_t)(k0 + sk + 2 * i) * 1024 + n0 + sr]);
                float w1 = __ldg(&Wx[(size_t)(k0 + sk + 2 * i + 1) * 1024 + n0 + sr]);
                *reinterpret_cast<__half2*>(&Bs[sr][sk + 2 * i]) = __floats2half2_rn(w0, w1);
            }
        }
        __syncthreads();

#pragma unroll
        for (int ks16 = 0; ks16 < 4; ks16++) {
            const int kc = ks16 * 16 + 2 * tg;
            unsigned a[2][4], b[8][2];
#pragma unroll
            for (int mt = 0; mt < 2; mt++) {
                const int r = wm + mt * 16 + g;
                a[mt][0] = *reinterpret_cast<const unsigned*>(&As[r][kc]);
                a[mt][1] = *reinterpret_cast<const unsigned*>(&As[r + 8][kc]);
                a[mt][2] = *reinterpret_cast<const unsigned*>(&As[r][kc + 8]);
                a[mt][3] = *reinterpret_cast<const unsigned*>(&As[r + 8][kc + 8]);
            }
#pragma unroll
            for (int nt = 0; nt < 8; nt++) {
                const int c = wn + nt * 8 + g;
                b[nt][0] = *reinterpret_cast<const unsigned*>(&Bs[c][kc]);
                b[nt][1] = *reinterpret_cast<const unsigned*>(&Bs[c][kc + 8]);
            }
#pragma unroll
            for (int mt = 0; mt < 2; mt++)
#pragma unroll
                for (int nt = 0; nt < 8; nt++) {
                    asm volatile(
                        "mma.sync.aligned.m16n8k16.row.col.f32.f16.f16.f32 "
                        "{%0,%1,%2,%3}, {%4,%5,%6,%7}, {%8,%9}, {%0,%1,%2,%3};"
                        : "+f"(d[mt][nt][0]), "+f"(d[mt][nt][1]),
                          "+f"(d[mt][nt][2]), "+f"(d[mt][nt][3])
                        : "r"(a[mt][0]), "r"(a[mt][1]), "r"(a[mt][2]), "r"(a[mt][3]),
                          "r"(b[nt][0]), "r"(b[nt][1]));
                }
        }
        __syncthreads();
    }

#pragma unroll
    for (int mt = 0; mt < 2; mt++) {
        const int r0 = m0 + wm + mt * 16 + g;
#pragma unroll
        for (int nt = 0; nt < 8; nt++) {
            const int c = n0 + wn + nt * 8 + 2 * tg;
            const float b0 = __ldg(&bias[c]);
            const float b1 = __ldg(&bias[c + 1]);
            float2 o0 = {d[mt][nt][0] + b0, d[mt][nt][1] + b1};
            float2 o1 = {d[mt][nt][2] + b0, d[mt][nt][3] + b1};
            *reinterpret_cast<float2*>(&g_xz[(size_t)r0 * 1024 + c])       = o0;
            *reinterpret_cast<float2*>(&g_xz[(size_t)(r0 + 8) * 1024 + c]) = o1;
        }
    }
}

// ---------------------------------------------------------------------------
// Kernel 2: LSTM scan. 8 clusters x 4 CTAs; 8 batches/cluster.
// 512 THREADS / 16 WARPS per CTA; warp w owns units [4w,4w+4) x 4 gates
// (16 Wh cols) as ONE m16n8k16 col-tile -> 64 weight regs/thread (~110 total,
// NO 255-reg cap / no spills). Gate-interleaved rows (r = 4*u_off + gate) make
// z, gates, cell state and h-scatter warp-local. Sync = dual parity mbarriers
// + st.async complete_tx (R13 scheme). No __syncthreads in the loop.
// ---------------------------------------------------------------------------
__device__ __forceinline__ float tanhapx(float x) {
    float y;
    asm("tanh.approx.f32 %0, %1;" : "=f"(y) : "f"(x));
    return y;
}
__device__ __forceinline__ float sigapx(float x) {
    return fmaf(tanhapx(0.5f * x), 0.5f, 0.5f);
}

#define TX_BYTES 4096u  // received per CTA per step: 4 CTAs x 256 h-words x 4 B
#define ZST 40          // zw unit stride: even (float2-aligned), 40%32=8 -> reads conflict-free

__global__ __launch_bounds__(512, 1) __cluster_dims__(4, 1, 1)
void lstm_scan_mma(const float* __restrict__ Wh,
                   const float* __restrict__ h0,
                   const float* __restrict__ c0,
                   float* __restrict__ out)
{
    __shared__ unsigned hh2[2][128][8];                 // [parity][k2][batch] fp16x2 (8 KB)
    __shared__ alignas(16) float zw[16][4 * ZST];       // per-warp z: u*ZST + gate*8 + b (10 KB)
    __shared__ alignas(8) unsigned long long mbars[2];

    const int tid  = threadIdx.x;
    const int warp = tid >> 5;    // 0..15
    const int lane = tid & 31;
    const int g    = lane >> 2;   // 0..7
    const int tg   = lane & 3;    // 0..3

    unsigned rank;
    asm("mov.u32 %0, %%cluster_ctarank;" : "=r"(rank));
    const int b0    = (blockIdx.x >> 2) * 8;
    const int ubase = (int)rank * 64;

    // Warp's col-tile: row r -> unit ubase + 4*warp + (r>>2), gate r&3.
    // Thread holds rows g (unit off g>>2) and g+8 (unit off (g>>2)+2), gate g&3.
    const int cgA = (g & 3) * 256 + ubase + 4 * warp + (g >> 2);      // row g col
    const int cgB = cgA + 2;                                          // row g+8 col

    // ---- mbarrier init + initial arming ----
    const unsigned mbase = (unsigned)__cvta_generic_to_shared(&mbars[0]);
    if (tid == 0) {
        asm volatile("mbarrier.init.shared.b64 [%0], 1;" :: "r"(mbase) : "memory");
        asm volatile("mbarrier.init.shared.b64 [%0], 1;" :: "r"(mbase + 8) : "memory");
        asm volatile("mbarrier.arrive.expect_tx.shared.b64 _, [%0], %1;"
                     :: "r"(mbase), "r"(TX_BYTES) : "memory");
        asm volatile("mbarrier.arrive.expect_tx.shared.b64 _, [%0], %1;"
                     :: "r"(mbase + 8), "r"(TX_BYTES) : "memory");
    }

    // ---- Wh as stationary A-fragments (fp16): ONE tile, 16 k-steps = 64 regs ----
    unsigned wa[16][4];
#pragma unroll
    for (int kt = 0; kt < 16; kt++) {
        const int k0 = kt * 16 + 2 * tg;
        wa[kt][0] = pack_h2(Wh[(size_t)(k0    ) * 1024 + cgA],
                            Wh[(size_t)(k0 + 1) * 1024 + cgA]);
        wa[kt][1] = pack_h2(Wh[(size_t)(k0    ) * 1024 + cgB],
                            Wh[(size_t)(k0 + 1) * 1024 + cgB]);
        wa[kt][2] = pack_h2(Wh[(size_t)(k0 + 8) * 1024 + cgA],
                            Wh[(size_t)(k0 + 9) * 1024 + cgA]);
        wa[kt][3] = pack_h2(Wh[(size_t)(k0 + 8) * 1024 + cgB],
                            Wh[(size_t)(k0 + 9) * 1024 + cgB]);
    }

    // ---- Init h buffer (parity 0) ----
    for (int i = tid; i < 128 * 8; i += 512) {
        const int k2 = i >> 3, b = i & 7;
        hh2[0][k2][b] = pack_h2(h0[(size_t)(b0 + b) * 256 + 2 * k2],
                                h0[(size_t)(b0 + b) * 256 + 2 * k2 + 1]);
    }

    // ---- Updater role: lane -> (unit off u_l = lane>>3, batch b_l = lane&7) ----
    const int u_l = lane >> 3;                 // 0..3
    const int b_l = lane & 7;                  // 0..7
    const int gu  = ubase + 4 * warp + u_l;    // global unit
    float creg = c0[(size_t)(b0 + b_l) * 256 + gu];

    const unsigned hbase = (unsigned)__cvta_generic_to_shared(&hh2[0][0][0]);

    // Preload xz for t=0 (4 accumulator slots: rows g/g+8 x batches 2tg,2tg+1)
    const float* xzA = g_xz + (size_t)(b0 + 2 * tg) * T_ * 1024;      // batch 2tg
    const float* xzB = xzA + (size_t)T_ * 1024;                       // batch 2tg+1
    float xzr[4];
    xzr[0] = __ldg(xzA + cgA);
    xzr[1] = __ldg(xzB + cgA);
    xzr[2] = __ldg(xzA + cgB);
    xzr[3] = __ldg(xzB + cgB);

    __syncthreads();
    asm volatile("barrier.cluster.arrive.aligned;" ::: "memory");
    asm volatile("barrier.cluster.wait.aligned;" ::: "memory");

    int ph0 = 0, ph1 = 0;

    for (int t = 0; t < T_; t++) {
        const int p = t & 1;

        float d[4], e[4];
#pragma unroll
        for (int q = 0; q < 4; q++) { d[q] = xzr[q]; e[q] = 0.f; }

        // ---- Wait for this parity's h traffic ----
        if (t > 0) {
            const unsigned mb = mbase + (unsigned)(p * 8);
            const int par = p ? ph1 : ph0;
            unsigned done;
            asm volatile(
                "{\n\t.reg .pred P1;\n\t"
                "mbarrier.try_wait.parity.acquire.cluster.shared::cta.b64 P1, [%1], %2;\n\t"
                "selp.b32 %0, 1, 0, P1;\n\t}"
                : "=r"(done) : "r"(mb), "r"(par) : "memory");
            if (!done) {
                asm volatile(
                    "{\n\t.reg .pred P1;\n\t"
                    "WAIT_%=:\n\t"
                    "mbarrier.try_wait.parity.acquire.cluster.shared::cta.b64 P1, [%0], %1, 0x989680;\n\t"
                    "@P1 bra.uni DONE_%=;\n\t"
                    "bra.uni WAIT_%=;\n\t"
                    "DONE_%=:\n\t}"
                    :: "r"(mb), "r"(par) : "memory");
            }
            if (p) ph1 ^= 1; else ph0 ^= 1;
            if (tid == 0)
                asm volatile("mbarrier.arrive.expect_tx.shared.b64 _, [%0], %1;"
                             :: "r"(mb), "r"(TX_BYTES) : "memory");
        }

        // Prefetch xz for t+1 (hidden behind MMA + gates + scatter)
        {
            const size_t off = (size_t)((t + 1 < T_) ? (t + 1) : t) * 1024;
            xzr[0] = __ldg(xzA + off + cgA);
            xzr[1] = __ldg(xzB + off + cgA);
            xzr[2] = __ldg(xzA + off + cgB);
            xzr[3] = __ldg(xzB + off + cgB);
        }

        // ---- z += h @ Wh : 16 k-tiles, one mma each, split d/e chains ----
        const unsigned hp = hbase + (unsigned)(p * 4096);
#pragma unroll
        for (int kt = 0; kt < 16; kt++) {
            unsigned bw0, bw1;
            asm volatile("ld.shared.u32 %0, [%1];"
                         : "=r"(bw0) : "r"(hp + (unsigned)(((kt * 8 + tg) * 8 + g) * 4)));
            asm volatile("ld.shared.u32 %0, [%1];"
                         : "=r"(bw1) : "r"(hp + (unsigned)(((kt * 8 + 4 + tg) * 8 + g) * 4)));
            if (kt < 8) {
                asm volatile(
                    "mma.sync.aligned.m16n8k16.row.col.f32.f16.f16.f32 "
                    "{%0,%1,%2,%3}, {%4,%5,%6,%7}, {%8,%9}, {%0,%1,%2,%3};"
                    : "+f"(d[0]), "+f"(d[1]), "+f"(d[2]), "+f"(d[3])
                    : "r"(wa[kt][0]), "r"(wa[kt][1]), "r"(wa[kt][2]), "r"(wa[kt][3]),
                      "r"(bw0), "r"(bw1));
            } else {
                asm volatile(
                    "mma.sync.aligned.m16n8k16.row.col.f32.f16.f16.f32 "
                    "{%0,%1,%2,%3}, {%4,%5,%6,%7}, {%8,%9}, {%0,%1,%2,%3};"
                    : "+f"(e[0]), "+f"(e[1]), "+f"(e[2]), "+f"(e[3])
                    : "r"(wa[kt][0]), "r"(wa[kt][1]), "r"(wa[kt][2]), "r"(wa[kt][3]),
                      "r"(bw0), "r"(bw1));
            }
        }

        // ---- WARP-LOCAL z exchange: zw[warp][u*ZST + gate*8 + b] ----
        float* zp = zw[warp];
        {
            const int i0 = (g >> 2) * ZST + (g & 3) * 8 + 2 * tg;
            float2 lo = {d[0] + e[0], d[1] + e[1]};
            float2 hi = {d[2] + e[2], d[3] + e[3]};
            *reinterpret_cast<float2*>(&zp[i0])            = lo;   // unit off g>>2
            *reinterpret_cast<float2*>(&zp[i0 + 2 * ZST])  = hi;   // unit off (g>>2)+2
        }
        __syncwarp();

        // ---- Gates + cell update (1 unit x 1 batch per lane) ----
        float hv;
        {
            const int zi0 = u_l * ZST + b_l;
            float zi = zp[zi0],      zf = zp[zi0 + 8];
            float zg = zp[zi0 + 16], zo = zp[zi0 + 24];
            float gi = sigapx(zi), gf = sigapx(zf);
            float gg = tanhapx(zg), go = sigapx(zo);
            creg = gf * creg + gi * gg;
            hv = go * tanhapx(creg);
        }
        __syncwarp();

        // ---- Pair with unit^1 (lane^8), even-gu lanes scatter the k-pair word ----
        {
            float po = __shfl_xor_sync(0xffffffffu, hv, 8);
            if ((gu & 1) == 0) {
                const unsigned hw = pack_h2(hv, po);
                const int np = p ^ 1;
                const unsigned doff = hbase +
                    (unsigned)(np * 4096 + ((gu >> 1) * 8 + b_l) * 4);
                const unsigned moff = mbase + (unsigned)(np * 8);
#pragma unroll
                for (unsigned rr = 0; rr < 4; rr++) {
                    unsigned ra, rb;
                    asm("mapa.shared::cluster.u32 %0, %1, %2;" : "=r"(ra) : "r"(doff), "r"(rr));
                    asm("mapa.shared::cluster.u32 %0, %1, %2;" : "=r"(rb) : "r"(moff), "r"(rr));
                    asm volatile(
                        "st.async.weak.shared::cluster.mbarrier::complete_tx::bytes.b32 [%0], %1, [%2];"
                        :: "r"(ra), "r"(hw), "r"(rb) : "memory");
                }
            }
        }

        // ---- Output store (unfenced) ----
        out[((size_t)(b0 + b_l) * T_ + t) * 256 + gu] = hv;
    }

    // Drain final parity-0 traffic, then exit rendezvous.
    asm volatile(
        "{\n\t.reg .pred P1;\n\t"
        "WAITF_%=:\n\t"
        "mbarrier.try_wait.parity.acquire.cluster.shared::cta.b64 P1, [%0], %1, 0x989680;\n\t"
        "@P1 bra.uni DONEF_%=;\n\t"
        "bra.uni WAITF_%=;\n\t"
        "DONEF_%=:\n\t}"
        :: "r"(mbase), "r"(ph0) : "memory");
    asm volatile("barrier.cluster.arrive.aligned;" ::: "memory");
    asm volatile("barrier.cluster.wait.aligned;" ::: "memory");
}

// ---------------------------------------------------------------------------
extern "C" void kernel_launch(void* const* d_in, const int* in_sizes, int n_in,
                              void* d_out, int out_size)
{
    const float* x    = (const float*)d_in[0];
    const float* Wx   = (const float*)d_in[1];
    const float* Wh   = (const float*)d_in[2];
    const float* bias = (const float*)d_in[3];
    const float* h0   = (const float*)d_in[4];
    const float* c0   = (const float*)d_in[5];
    float* out = (float*)d_out;

    // Phase 1: input projection (fp16 tensor cores)
    dim3 g1(1024 / 128, (B_ * T_) / 128);  // (8, 1024)
    gemm_xz_mma<<<g1, 256>>>(x, Wx, bias);

    // Phase 2: recurrent scan (8 clusters of 4 CTAs, 8 batches each, 512 thr)
    lstm_scan_mma<<<32, 512>>>(Wh, h0, c0, out);
}

// round 17
// speedup vs baseline: 1.1679x; 1.1679x over previous
#include <cuda_runtime.h>
#include <cuda_fp16.h>
#include <cstdint>

// Problem dims (fixed by the dataset)
#define B_ 64
#define T_ 2048
#define I_ 256
#define H_ 256
#define G4_ 1024  // 4*H

// Scratch for xz = x@Wx + b : [B,T,4H] fp32 (537 MB) + per-t-chunk progress.
__device__ float g_xz[(size_t)B_ * T_ * G4_];
__device__ unsigned g_flag[16];   // tiles completed per 128-step chunk (target 512)

// Pack two floats into fp16x2 bits (full 32-bit, both halves)
__device__ __forceinline__ unsigned pack_h2(float a, float b) {
    __half2 h = __floats2half2_rn(a, b);
    return *reinterpret_cast<unsigned*>(&h);
}

__device__ __forceinline__ float tanhapx(float x) {
    float y;
    asm("tanh.approx.f32 %0, %1;" : "=f"(y) : "f"(x));
    return y;
}
__device__ __forceinline__ float sigapx(float x) {
    return fmaf(tanhapx(0.5f * x), 0.5f, 0.5f);
}

#define ZSTRIDE 260
#define TX_BYTES 4096u
#define NPROD 116          // GEMM-producer CTAs (32..147)
#define NTILES 8192        // 1024 m-tiles x 8 n-tiles

// Shared memory: union of the two roles
struct SmemScan {
    unsigned hh2[2][128][8];                  // [parity][k2][batch] fp16x2
    float zbuf[8][ZSTRIDE];
    alignas(8) unsigned long long mbars[2];
};
struct SmemGemm {
    alignas(16) __half As[128][72];
    alignas(16) __half Bs[128][72];
};

__global__ void zero_flags_kernel() {
    if (threadIdx.x < 16) g_flag[threadIdx.x] = 0u;
}

// ---------------------------------------------------------------------------
// Fused kernel: CTAs 0..31 = LSTM scan (R13 architecture), CTAs 32..147 =
// xz GEMM producers in t-chunk order with release-flag signalling.
// ---------------------------------------------------------------------------
__global__ __launch_bounds__(256, 1) __cluster_dims__(4, 1, 1)
void lstm_fused(const float* __restrict__ x,
                const float* __restrict__ Wx,
                const float* __restrict__ bias,
                const float* __restrict__ Wh,
                const float* __restrict__ h0,
                const float* __restrict__ c0,
                float* __restrict__ out)
{
    __shared__ union { SmemScan s; SmemGemm g; } su;

    const int tid  = threadIdx.x;
    const int warp = tid >> 5;
    const int lane = tid & 31;
    const int g    = lane >> 2;   // 0..7
    const int tg   = lane & 3;    // 0..3

    if (blockIdx.x >= 32) {
        // =================== GEMM producer path ===================
        __half (*As)[72] = su.g.As;
        __half (*Bs)[72] = su.g.Bs;
        const int wm = (warp & 3) * 32;
        const int wn = (warp >> 2) * 64;
        const int sr = tid >> 1;
        const int sk = (tid & 1) * 32;

        for (int idx = (int)blockIdx.x - 32; idx < NTILES; idx += NPROD) {
            const int chunk  = idx >> 9;          // /512 : t-chunk (128 steps)
            const int within = idx & 511;
            const int bb     = within >> 3;       // batch 0..63
            const int nt     = within & 7;        // n-tile
            const int m0 = bb * 2048 + chunk * 128;
            const int n0 = nt * 128;

            float d[2][8][4];
#pragma unroll
            for (int mt = 0; mt < 2; mt++)
#pragma unroll
                for (int ntt = 0; ntt < 8; ntt++)
#pragma unroll
                    for (int q = 0; q < 4; q++) d[mt][ntt][q] = 0.f;

            for (int k0 = 0; k0 < 256; k0 += 64) {
                {
                    const float4* xp = reinterpret_cast<const float4*>(
                        &x[(size_t)(m0 + sr) * 256 + k0 + sk]);
#pragma unroll
                    for (int i = 0; i < 8; i++) {
                        float4 v = xp[i];
                        *reinterpret_cast<__half2*>(&As[sr][sk + 4 * i])     = __floats2half2_rn(v.x, v.y);
                        *reinterpret_cast<__half2*>(&As[sr][sk + 4 * i + 2]) = __floats2half2_rn(v.z, v.w);
                    }
                }
                {
#pragma unroll
                    for (int i = 0; i < 16; i++) {
                        float w0 = __ldg(&Wx[(size_t)(k0 + sk + 2 * i) * 1024 + n0 + sr]);
                        float w1 = __ldg(&Wx[(size_t)(k0 + sk + 2 * i + 1) * 1024 + n0 + sr]);
                        *reinterpret_cast<__half2*>(&Bs[sr][sk + 2 * i]) = __floats2half2_rn(w0, w1);
                    }
                }
                __syncthreads();

#pragma unroll
                for (int ks16 = 0; ks16 < 4; ks16++) {
                    const int kc = ks16 * 16 + 2 * tg;
                    unsigned a[2][4], b[8][2];
#pragma unroll
                    for (int mt = 0; mt < 2; mt++) {
                        const int r = wm + mt * 16 + g;
                        a[mt][0] = *reinterpret_cast<const unsigned*>(&As[r][kc]);
                        a[mt][1] = *reinterpret_cast<const unsigned*>(&As[r + 8][kc]);
                        a[mt][2] = *reinterpret_cast<const unsigned*>(&As[r][kc + 8]);
                        a[mt][3] = *reinterpret_cast<const unsigned*>(&As[r + 8][kc + 8]);
                    }
#pragma unroll
                    for (int ntt = 0; ntt < 8; ntt++) {
                        const int c = wn + ntt * 8 + g;
                        b[ntt][0] = *reinterpret_cast<const unsigned*>(&Bs[c][kc]);
                        b[ntt][1] = *reinterpret_cast<const unsigned*>(&Bs[c][kc + 8]);
                    }
#pragma unroll
                    for (int mt = 0; mt < 2; mt++)
#pragma unroll
                        for (int ntt = 0; ntt < 8; ntt++) {
                            asm volatile(
                                "mma.sync.aligned.m16n8k16.row.col.f32.f16.f16.f32 "
                                "{%0,%1,%2,%3}, {%4,%5,%6,%7}, {%8,%9}, {%0,%1,%2,%3};"
                                : "+f"(d[mt][ntt][0]), "+f"(d[mt][ntt][1]),
                                  "+f"(d[mt][ntt][2]), "+f"(d[mt][ntt][3])
                                : "r"(a[mt][0]), "r"(a[mt][1]), "r"(a[mt][2]), "r"(a[mt][3]),
                                  "r"(b[ntt][0]), "r"(b[ntt][1]));
                        }
                }
                __syncthreads();
            }

#pragma unroll
            for (int mt = 0; mt < 2; mt++) {
                const int r0 = m0 + wm + mt * 16 + g;
#pragma unroll
                for (int ntt = 0; ntt < 8; ntt++) {
                    const int c = n0 + wn + ntt * 8 + 2 * tg;
                    const float b0v = __ldg(&bias[c]);
                    const float b1v = __ldg(&bias[c + 1]);
                    float2 o0 = {d[mt][ntt][0] + b0v, d[mt][ntt][1] + b1v};
                    float2 o1 = {d[mt][ntt][2] + b0v, d[mt][ntt][3] + b1v};
                    *reinterpret_cast<float2*>(&g_xz[(size_t)r0 * 1024 + c])       = o0;
                    *reinterpret_cast<float2*>(&g_xz[(size_t)(r0 + 8) * 1024 + c]) = o1;
                }
            }

            // Publish: all stores fenced, then one counter bump for this chunk
            __threadfence();
            __syncthreads();
            if (tid == 0) atomicAdd(&g_flag[chunk], 1u);
        }
        return;
    }

    // =================== Scan path (R13, + chunk-flag gating) ===================
    unsigned (*hh2)[128][8] = su.s.hh2;
    float (*zbuf)[ZSTRIDE]  = su.s.zbuf;

    unsigned rank;
    asm("mov.u32 %0, %%cluster_ctarank;" : "=r"(rank));
    const int b0    = ((int)blockIdx.x >> 2) * 8;
    const int ubase = (int)rank * 64;

    int cg[2], cg8[2];
#pragma unroll
    for (int c2 = 0; c2 < 2; c2++) {
        const int ct = warp + 8 * c2;
        const int gate = ct >> 2;
        const int u0 = (ct & 3) * 16;
        cg[c2]  = gate * 256 + ubase + u0 + g;
        cg8[c2] = cg[c2] + 8;
    }

    const unsigned mbase = (unsigned)__cvta_generic_to_shared(&su.s.mbars[0]);
    if (tid == 0) {
        asm volatile("mbarrier.init.shared.b64 [%0], 1;" :: "r"(mbase) : "memory");
        asm volatile("mbarrier.init.shared.b64 [%0], 1;" :: "r"(mbase + 8) : "memory");
        asm volatile("mbarrier.arrive.expect_tx.shared.b64 _, [%0], %1;"
                     :: "r"(mbase), "r"(TX_BYTES) : "memory");
        asm volatile("mbarrier.arrive.expect_tx.shared.b64 _, [%0], %1;"
                     :: "r"(mbase + 8), "r"(TX_BYTES) : "memory");
    }

    unsigned wa[2][16][4];
#pragma unroll
    for (int c2 = 0; c2 < 2; c2++) {
#pragma unroll
        for (int kt = 0; kt < 16; kt++) {
            const int k0 = kt * 16 + 2 * tg;
            wa[c2][kt][0] = pack_h2(Wh[(size_t)(k0    ) * 1024 + cg[c2]],
                                    Wh[(size_t)(k0 + 1) * 1024 + cg[c2]]);
            wa[c2][kt][1] = pack_h2(Wh[(size_t)(k0    ) * 1024 + cg8[c2]],
                                    Wh[(size_t)(k0 + 1) * 1024 + cg8[c2]]);
            wa[c2][kt][2] = pack_h2(Wh[(size_t)(k0 + 8) * 1024 + cg[c2]],
                                    Wh[(size_t)(k0 + 9) * 1024 + cg[c2]]);
            wa[c2][kt][3] = pack_h2(Wh[(size_t)(k0 + 8) * 1024 + cg8[c2]],
                                    Wh[(size_t)(k0 + 9) * 1024 + cg8[c2]]);
        }
    }

    for (int i = tid; i < 128 * 8; i += 256) {
        const int k2 = i >> 3, b = i & 7;
        hh2[0][k2][b] = pack_h2(h0[(size_t)(b0 + b) * 256 + 2 * k2],
                                h0[(size_t)(b0 + b) * 256 + 2 * k2 + 1]);
    }

    const int b_u = warp;
    const int u2  = lane;
    const int gu0 = ubase + 2 * u2;
    float creg0 = c0[(size_t)(b0 + b_u) * 256 + gu0];
    float creg1 = c0[(size_t)(b0 + b_u) * 256 + gu0 + 1];

    const unsigned hbase = (unsigned)__cvta_generic_to_shared(&hh2[0][0][0]);
    const int k2u = (ubase >> 1) + u2;

    const float* xzA = &g_xz[(size_t)(b0 + 2 * tg)     * T_ * 1024];
    const float* xzB = &g_xz[(size_t)(b0 + 2 * tg + 1) * T_ * 1024];

    // ---- Wait for xz chunk 0 (producers) before the t=0 preload ----
    if (tid == 0) {
        unsigned v;
        do {
            asm volatile("ld.acquire.gpu.global.u32 %0, [%1];"
                         : "=r"(v) : "l"(&g_flag[0]) : "memory");
        } while (v < 512u);
    }
    __syncthreads();

    float xzr[2][4];
#pragma unroll
    for (int c2 = 0; c2 < 2; c2++) {
        xzr[c2][0] = __ldg(xzA + cg[c2]);
        xzr[c2][1] = __ldg(xzB + cg[c2]);
        xzr[c2][2] = __ldg(xzA + cg8[c2]);
        xzr[c2][3] = __ldg(xzB + cg8[c2]);
    }

    __syncthreads();
    asm volatile("barrier.cluster.arrive.aligned;" ::: "memory");
    asm volatile("barrier.cluster.wait.aligned;" ::: "memory");

    int ph0 = 0, ph1 = 0;

    for (int t = 0; t < T_; t++) {
        const int p = t & 1;

        float d[2][4], e[2][4];
#pragma unroll
        for (int c2 = 0; c2 < 2; c2++)
#pragma unroll
            for (int q = 0; q < 4; q++) { d[c2][q] = xzr[c2][q]; e[c2][q] = 0.f; }

        if (t > 0) {
            const unsigned mb = mbase + (unsigned)(p * 8);
            const int par = p ? ph1 : ph0;
            unsigned done;
            asm volatile(
                "{\n\t.reg .pred P1;\n\t"
                "mbarrier.try_wait.parity.acquire.cluster.shared::cta.b64 P1, [%1], %2;\n\t"
                "selp.b32 %0, 1, 0, P1;\n\t}"
                : "=r"(done) : "r"(mb), "r"(par) : "memory");
            if (!done) {
                asm volatile(
                    "{\n\t.reg .pred P1;\n\t"
                    "WAIT_%=:\n\t"
                    "mbarrier.try_wait.parity.acquire.cluster.shared::cta.b64 P1, [%0], %1, 0x989680;\n\t"
                    "@P1 bra.uni DONE_%=;\n\t"
                    "bra.uni WAIT_%=;\n\t"
                    "DONE_%=:\n\t}"
                    :: "r"(mb), "r"(par) : "memory");
            }
            if (p) ph1 ^= 1; else ph0 ^= 1;
            if (tid == 0)
                asm volatile("mbarrier.arrive.expect_tx.shared.b64 _, [%0], %1;"
                             :: "r"(mb), "r"(TX_BYTES) : "memory");
        }

        // ---- Gate the t+1 prefetch on its producer chunk, then prefetch ----
        {
            const int tn = (t + 1 < T_) ? (t + 1) : t;
            if ((tn & 127) == 0 && tn == t + 1) {
                const int chunk = tn >> 7;
                if (tid == 0) {
                    unsigned v;
                    do {
                        asm volatile("ld.acquire.gpu.global.u32 %0, [%1];"
                                     : "=r"(v) : "l"(&g_flag[chunk]) : "memory");
                    } while (v < 512u);
                }
                __syncthreads();
            }
            const size_t off = (size_t)tn * 1024;
#pragma unroll
            for (int c2 = 0; c2 < 2; c2++) {
                xzr[c2][0] = __ldg(xzA + off + cg[c2]);
                xzr[c2][1] = __ldg(xzB + off + cg[c2]);
                xzr[c2][2] = __ldg(xzA + off + cg8[c2]);
                xzr[c2][3] = __ldg(xzB + off + cg8[c2]);
            }
        }

        // ---- z += h @ Wh ----
        const unsigned hp = hbase + (unsigned)(p * 4096);
#pragma unroll
        for (int kt = 0; kt < 16; kt++) {
            unsigned bw0, bw1;
            asm volatile("ld.shared.u32 %0, [%1];"
                         : "=r"(bw0) : "r"(hp + (unsigned)(((kt * 8 + tg) * 8 + g) * 4)));
            asm volatile("ld.shared.u32 %0, [%1];"
                         : "=r"(bw1) : "r"(hp + (unsigned)(((kt * 8 + 4 + tg) * 8 + g) * 4)));
            float (*acc)[4] = (kt < 8) ? d : e;
#pragma unroll
            for (int c2 = 0; c2 < 2; c2++) {
                asm volatile(
                    "mma.sync.aligned.m16n8k16.row.col.f32.f16.f16.f32 "
                    "{%0,%1,%2,%3}, {%4,%5,%6,%7}, {%8,%9}, {%0,%1,%2,%3};"
                    : "+f"(acc[c2][0]), "+f"(acc[c2][1]), "+f"(acc[c2][2]), "+f"(acc[c2][3])
                    : "r"(wa[c2][kt][0]), "r"(wa[c2][kt][1]),
                      "r"(wa[c2][kt][2]), "r"(wa[c2][kt][3]),
                      "r"(bw0), "r"(bw1));
            }
        }

        // ---- Merge + scatter z ----
#pragma unroll
        for (int c2 = 0; c2 < 2; c2++) {
            const int lc = (warp + 8 * c2) * 16;
            zbuf[2 * tg    ][lc + g]     = d[c2][0] + e[c2][0];
            zbuf[2 * tg + 1][lc + g]     = d[c2][1] + e[c2][1];
            zbuf[2 * tg    ][lc + g + 8] = d[c2][2] + e[c2][2];
            zbuf[2 * tg + 1][lc + g + 8] = d[c2][3] + e[c2][3];
        }
        __syncthreads();

        // ---- Gates + cell update ----
        float h0v, h1v;
        {
            const float* zb = zbuf[b_u];
            float2 vi = *reinterpret_cast<const float2*>(&zb[      2 * u2]);
            float2 vf = *reinterpret_cast<const float2*>(&zb[ 64 + 2 * u2]);
            float2 vg = *reinterpret_cast<const float2*>(&zb[128 + 2 * u2]);
            float2 vo = *reinterpret_cast<const float2*>(&zb[192 + 2 * u2]);

            float gi = sigapx(vi.x), gf = sigapx(vf.x);
            float gg = tanhapx(vg.x), go = sigapx(vo.x);
            creg0 = gf * creg0 + gi * gg;
            h0v = go * tanhapx(creg0);

            gi = sigapx(vi.y); gf = sigapx(vf.y);
            gg = tanhapx(vg.y); go = sigapx(vo.y);
            creg1 = gf * creg1 + gi * gg;
            h1v = go * tanhapx(creg1);
        }

        // ---- h-scatter via st.async ----
        {
            const unsigned hw = pack_h2(h0v, h1v);
            const int np = p ^ 1;
            const unsigned doff = hbase + (unsigned)(np * 4096 + (k2u * 8 + b_u) * 4);
            const unsigned moff = mbase + (unsigned)(np * 8);
#pragma unroll
            for (unsigned rr = 0; rr < 4; rr++) {
                unsigned ra, rb;
                asm("mapa.shared::cluster.u32 %0, %1, %2;" : "=r"(ra) : "r"(doff), "r"(rr));
                asm("mapa.shared::cluster.u32 %0, %1, %2;" : "=r"(rb) : "r"(moff), "r"(rr));
                asm volatile(
                    "st.async.weak.shared::cluster.mbarrier::complete_tx::bytes.b32 [%0], %1, [%2];"
                    :: "r"(ra), "r"(hw), "r"(rb) : "memory");
            }
        }

        // ---- Output store (unfenced) ----
        {
            float2 ov = {h0v, h1v};
            *reinterpret_cast<float2*>(
                &out[((size_t)(b0 + b_u) * T_ + t) * 256 + gu0]) = ov;
        }
    }

    // Drain final traffic; exit rendezvous.
    asm volatile(
        "{\n\t.reg .pred P1;\n\t"
        "WAITF_%=:\n\t"
        "mbarrier.try_wait.parity.acquire.cluster.shared::cta.b64 P1, [%0], %1, 0x989680;\n\t"
        "@P1 bra.uni DONEF_%=;\n\t"
        "bra.uni WAITF_%=;\n\t"
        "DONEF_%=:\n\t}"
        :: "r"(mbase), "r"(ph0) : "memory");
    asm volatile("barrier.cluster.arrive.aligned;" ::: "memory");
    asm volatile("barrier.cluster.wait.aligned;" ::: "memory");
}

// ---------------------------------------------------------------------------
extern "C" void kernel_launch(void* const* d_in, const int* in_sizes, int n_in,
                              void* d_out, int out_size)
{
    const float* x    = (const float*)d_in[0];
    const float* Wx   = (const float*)d_in[1];
    const float* Wh   = (const float*)d_in[2];
    const float* bias = (const float*)d_in[3];
    const float* h0   = (const float*)d_in[4];
    const float* c0   = (const float*)d_in[5];
    float* out = (float*)d_out;

    zero_flags_kernel<<<1, 32>>>();
    lstm_fused<<<148, 256>>>(x, Wx, bias, Wh, h0, c0, out);
}